// round 1
// baseline (speedup 1.0000x reference)
#include <cuda_runtime.h>
#include <cuda_bf16.h>

// PCEN: out = (x / (FLOOR + ema)^a + d)^(1/root) - d^(1/root)
// ema_t = w*x_t + (1-w)*ema_{t-1},  ema_0 = x_0  (per (B,C) row along T)
//
// Shapes fixed by setup_inputs: B=128, C=64, T=8000.
// One CTA per row. Affine block scan for the EMA (exact, no truncation).

constexpr int   kT       = 8000;
constexpr int   kChunk   = 25;            // 25 coprime with 32 -> conflict-free smem
constexpr int   kThreads = 320;           // 320 * 25 == 8000
constexpr int   kWarps   = kThreads / 32; // 10
constexpr float kFloor   = 1e-6f;

__global__ __launch_bounds__(kThreads)
void pcen_kernel(const float* __restrict__ x,
                 const float* __restrict__ alpha,
                 const float* __restrict__ delta,
                 const float* __restrict__ root,
                 const float* __restrict__ ew,
                 float* __restrict__ out,
                 int C)
{
    __shared__ float sx[kT];
    __shared__ float sA[kWarps];
    __shared__ float sB[kWarps];

    const int tid  = threadIdx.x;
    const int lane = tid & 31;
    const int wid  = tid >> 5;
    const int row  = blockIdx.x;
    const int c    = row % C;

    const float w  = fminf(fmaxf(ew[c], 0.0f), 1.0f);
    const float q  = 1.0f - w;
    const float a  = fminf(alpha[c], 1.0f);
    const float d  = delta[c];
    const float r  = 1.0f / fmaxf(root[c], 1.0f);
    const float dr = __powf(d, r);

    // ---- stage row into smem (coalesced float4) ----
    const float4* __restrict__ x4 = reinterpret_cast<const float4*>(x + (size_t)row * kT);
    float4* s4 = reinterpret_cast<float4*>(sx);
    for (int i = tid; i < kT / 4; i += kThreads) s4[i] = x4[i];
    __syncthreads();

    const float x0 = sx[0];   // carry into the whole row (init of the scan)

    // ---- pass 1: per-thread affine reduce over its 25-element chunk ----
    // chunk as function of incoming carry c: acc_end = A*c + b
    const int off = tid * kChunk;
    float b = 0.0f;
    #pragma unroll
    for (int k = 0; k < kChunk; ++k)
        b = fmaf(q, b, w * sx[off + k]);
    const float q2 = q * q, q4 = q2 * q2, q8 = q4 * q4, q16 = q8 * q8;
    float A = q16 * q8 * q;   // q^25

    // ---- warp inclusive scan of (A,b):  cur ∘ prev = (A*Ap, A*bp + b) ----
    #pragma unroll
    for (int s = 1; s < 32; s <<= 1) {
        float Ap = __shfl_up_sync(0xffffffffu, A, s);
        float bp = __shfl_up_sync(0xffffffffu, b, s);
        if (lane >= s) { b = fmaf(A, bp, b); A *= Ap; }
    }
    if (lane == 31) { sA[wid] = A; sB[wid] = b; }
    __syncthreads();

    // ---- warp 0 scans the 10 warp aggregates ----
    if (wid == 0) {
        float Aw = (lane < kWarps) ? sA[lane] : 1.0f;
        float bw = (lane < kWarps) ? sB[lane] : 0.0f;
        #pragma unroll
        for (int s = 1; s < 16; s <<= 1) {
            float Ap = __shfl_up_sync(0xffffffffu, Aw, s);
            float bp = __shfl_up_sync(0xffffffffu, bw, s);
            if (lane >= s) { bw = fmaf(Aw, bp, bw); Aw *= Ap; }
        }
        if (lane < kWarps) { sA[lane] = Aw; sB[lane] = bw; }
    }
    __syncthreads();

    // ---- exclusive prefix for this thread ----
    float Ai = __shfl_up_sync(0xffffffffu, A, 1);
    float bi = __shfl_up_sync(0xffffffffu, b, 1);
    if (lane == 0) { Ai = 1.0f; bi = 0.0f; }
    float Aex = Ai, bex = bi;
    if (wid > 0) {
        const float Aw = sA[wid - 1], bw = sB[wid - 1];
        bex = fmaf(Ai, bw, bi);
        Aex = Ai * Aw;
    }
    float acc = fmaf(Aex, x0, bex);   // exact carry into this chunk

    // ---- pass 2: recompute EMA with carry + pointwise PCEN, write into smem ----
    #pragma unroll
    for (int k = 0; k < kChunk; ++k) {
        const float xv = sx[off + k];
        acc = fmaf(q, acc, w * xv);                 // ema_t
        const float p = __powf(kFloor + acc, -a);   // MUFU lg2+ex2
        const float u = fmaf(xv, p, d);             // x/(FLOOR+ema)^a + d
        sx[off + k] = __powf(u, r) - dr;
    }
    __syncthreads();

    // ---- coalesced float4 store ----
    float4* __restrict__ o4 = reinterpret_cast<float4*>(out + (size_t)row * kT);
    for (int i = tid; i < kT / 4; i += kThreads) o4[i] = s4[i];
}

extern "C" void kernel_launch(void* const* d_in, const int* in_sizes, int n_in,
                              void* d_out, int out_size)
{
    const float* x     = (const float*)d_in[0];
    const float* alpha = (const float*)d_in[1];
    const float* delta = (const float*)d_in[2];
    const float* root  = (const float*)d_in[3];
    const float* ew    = (const float*)d_in[4];
    float* out = (float*)d_out;

    const int C    = in_sizes[1];          // 64
    const int rows = in_sizes[0] / kT;     // B*C = 8192

    pcen_kernel<<<rows, kThreads>>>(x, alpha, delta, root, ew, out, C);
}

// round 2
// speedup vs baseline: 1.1832x; 1.1832x over previous
#include <cuda_runtime.h>
#include <cstdint>

// PCEN, persistent-CTA 3-stage pipeline:
//   ema_t = w*x_t + (1-w)*ema_{t-1}, ema_0 = x_0   (affine block scan, exact)
//   out   = (x/(FLOOR+ema)^a + d)^(1/root) - d^(1/root)
// B=128, C=64, T=8000. One row (8000 f32 = 32 KB) per pipeline slot.
// cp.async.bulk gmem->smem (mbarrier) overlapped with compute; TMA bulk store back.

constexpr int      kT        = 8000;
constexpr int      kChunk    = 25;            // 320*25 = 8000; 25 coprime 32 -> no bank conflicts
constexpr int      kThreads  = 320;
constexpr int      kWarps    = kThreads / 32; // 10
constexpr int      kNBuf     = 3;
constexpr float    kFloor    = 1e-6f;
constexpr unsigned kRowBytes = kT * 4;        // 32000

__device__ __forceinline__ uint32_t s2u(const void* p) {
    return (uint32_t)__cvta_generic_to_shared(p);
}

__device__ __forceinline__ float sqrt_apx(float v) {
    float r;
    asm("sqrt.approx.f32 %0, %1;" : "=f"(r) : "f"(v));
    return r;
}

__device__ __forceinline__ void bulk_load(uint32_t dst_smem, const void* src_gmem,
                                          uint32_t bytes, uint32_t mbar) {
    asm volatile(
        "cp.async.bulk.shared::cta.global.mbarrier::complete_tx::bytes [%0], [%1], %2, [%3];"
        :: "r"(dst_smem), "l"(src_gmem), "r"(bytes), "r"(mbar) : "memory");
}

__device__ __forceinline__ void mbar_expect_tx(uint32_t mbar, uint32_t bytes) {
    asm volatile("mbarrier.arrive.expect_tx.shared::cta.b64 _, [%0], %1;"
                 :: "r"(mbar), "r"(bytes) : "memory");
}

__device__ __forceinline__ void mbar_wait(uint32_t mbar, uint32_t phase) {
    asm volatile(
        "{\n\t.reg .pred P;\n"
        "W_%=:\n\t"
        "mbarrier.try_wait.parity.acquire.cta.shared::cta.b64 P, [%0], %1, 0x989680;\n\t"
        "@!P bra W_%=;\n\t}"
        :: "r"(mbar), "r"(phase) : "memory");
}

__global__ void __launch_bounds__(kThreads, 2)
pcen_kernel(const float* __restrict__ x,
            const float* __restrict__ alpha,
            const float* __restrict__ delta,
            const float* __restrict__ root,
            const float* __restrict__ ew,
            float* __restrict__ out,
            int C, int rows)
{
    extern __shared__ float smem[];                     // kNBuf * kT floats
    __shared__ __align__(8) unsigned long long mbar[kNBuf];
    __shared__ float sA[kWarps], sB[kWarps];

    const int tid  = threadIdx.x;
    const int lane = tid & 31;
    const int wid  = tid >> 5;
    const int stride = gridDim.x;

    if (tid == 0) {
        #pragma unroll
        for (int b = 0; b < kNBuf; ++b)
            asm volatile("mbarrier.init.shared::cta.b64 [%0], 1;"
                         :: "r"(s2u(&mbar[b])) : "memory");
    }
    __syncthreads();

    const int nIter = (rows - (int)blockIdx.x + stride - 1) / stride;

    // prologue: kick off first row's load
    if (tid == 0) {
        const uint32_t mb = s2u(&mbar[0]);
        mbar_expect_tx(mb, kRowBytes);
        bulk_load(s2u(smem), x + (size_t)blockIdx.x * kT, kRowBytes, mb);
    }

    int ph0 = 0, ph1 = 0, ph2 = 0;

    for (int it = 0; it < nIter; ++it) {
        const int row  = blockIdx.x + it * stride;
        const int bsel = it % kNBuf;
        float* sx = smem + bsel * kT;

        // issue next row's load (buffer reuse guarded: all stores except the
        // newest must have finished READING smem before we overwrite)
        if (tid == 0 && it + 1 < nIter) {
            const int nb = (it + 1) % kNBuf;
            asm volatile("cp.async.bulk.wait_group.read 1;" ::: "memory");
            const uint32_t mb = s2u(&mbar[nb]);
            mbar_expect_tx(mb, kRowBytes);
            bulk_load(s2u(smem + nb * kT), x + (size_t)(row + stride) * kT, kRowBytes, mb);
        }

        // per-row params (uniform across CTA)
        const int   c  = row % C;
        const float w  = fminf(fmaxf(ew[c], 0.0f), 1.0f);
        const float q  = 1.0f - w;
        const float a  = fminf(alpha[c], 1.0f);
        const float d  = delta[c];
        const float r  = 1.0f / fmaxf(root[c], 1.0f);
        const bool  rhalf = (r == 0.5f);
        const float dr = rhalf ? sqrt_apx(d) : __powf(d, r);
        const float na = -a;

        // wait for this row's data
        {
            const uint32_t mb = s2u(&mbar[bsel]);
            int ph = (bsel == 0) ? ph0 : (bsel == 1) ? ph1 : ph2;
            mbar_wait(mb, ph);
            if (bsel == 0) ph0 ^= 1; else if (bsel == 1) ph1 ^= 1; else ph2 ^= 1;
        }

        const float x0  = sx[0];
        const int   off = tid * kChunk;

        // pass 1: per-thread affine reduce (1 FMA/elem; scale by w once)
        float b = 0.0f;
        #pragma unroll
        for (int k = 0; k < kChunk; ++k)
            b = fmaf(q, b, sx[off + k]);
        b *= w;
        const float q2 = q*q, q4 = q2*q2, q8 = q4*q4, q16 = q8*q8;
        float A = q16 * q8 * q;   // q^25

        // warp inclusive scan of (A,b)
        #pragma unroll
        for (int s = 1; s < 32; s <<= 1) {
            float Ap = __shfl_up_sync(0xffffffffu, A, s);
            float bp = __shfl_up_sync(0xffffffffu, b, s);
            if (lane >= s) { b = fmaf(A, bp, b); A *= Ap; }
        }
        if (lane == 31) { sA[wid] = A; sB[wid] = b; }
        __syncthreads();

        if (wid == 0) {
            float Aw = (lane < kWarps) ? sA[lane] : 1.0f;
            float bw = (lane < kWarps) ? sB[lane] : 0.0f;
            #pragma unroll
            for (int s = 1; s < 16; s <<= 1) {
                float Ap = __shfl_up_sync(0xffffffffu, Aw, s);
                float bp = __shfl_up_sync(0xffffffffu, bw, s);
                if (lane >= s) { bw = fmaf(Aw, bp, bw); Aw *= Ap; }
            }
            if (lane < kWarps) { sA[lane] = Aw; sB[lane] = bw; }
        }
        __syncthreads();

        // exclusive prefix -> exact carry into this thread's chunk
        float Ai = __shfl_up_sync(0xffffffffu, A, 1);
        float bi = __shfl_up_sync(0xffffffffu, b, 1);
        if (lane == 0) { Ai = 1.0f; bi = 0.0f; }
        float Aex = Ai, bex = bi;
        if (wid > 0) {
            bex = fmaf(Ai, sB[wid - 1], bi);
            Aex = Ai * sA[wid - 1];
        }
        float acc = fmaf(Aex, x0, bex);

        // pass 2: EMA recompute + pointwise PCEN, results written in place
        #pragma unroll
        for (int k = 0; k < kChunk; ++k) {
            const float xv = sx[off + k];
            acc = fmaf(q, acc, w * xv);
            const float p = __powf(kFloor + acc, na);      // LG2+FMUL+EX2
            const float u = fmaf(xv, p, d);
            const float y = rhalf ? sqrt_apx(u) : __powf(u, r);
            sx[off + k] = y - dr;
        }
        __syncthreads();

        // async store smem -> gmem (overlaps next iteration's compute)
        if (tid == 0) {
            asm volatile("fence.proxy.async.shared::cta;" ::: "memory");
            asm volatile("cp.async.bulk.global.shared::cta.bulk_group [%0], [%1], %2;"
                         :: "l"(out + (size_t)row * kT), "r"(s2u(sx)), "r"(kRowBytes)
                         : "memory");
            asm volatile("cp.async.bulk.commit_group;" ::: "memory");
        }
    }

    if (tid == 0)
        asm volatile("cp.async.bulk.wait_group 0;" ::: "memory");
}

extern "C" void kernel_launch(void* const* d_in, const int* in_sizes, int n_in,
                              void* d_out, int out_size)
{
    const float* x     = (const float*)d_in[0];
    const float* alpha = (const float*)d_in[1];
    const float* delta = (const float*)d_in[2];
    const float* root  = (const float*)d_in[3];
    const float* ew    = (const float*)d_in[4];
    float* out = (float*)d_out;

    const int C    = in_sizes[1];            // 64
    const int rows = in_sizes[0] / kT;       // 8192

    const unsigned smemBytes = kNBuf * kRowBytes;   // 96000
    cudaFuncSetAttribute(pcen_kernel, cudaFuncAttributeMaxDynamicSharedMemorySize, smemBytes);

    int grid = 296;                          // 148 SMs x 2 CTAs, persistent
    if (grid > rows) grid = rows;

    pcen_kernel<<<grid, kThreads, smemBytes>>>(x, alpha, delta, root, ew, out, C, rows);
}